// round 1
// baseline (speedup 1.0000x reference)
#include <cuda_runtime.h>
#include <cstdint>

// Delta modulation encoder: 512 independent serial scans of length 131072.
// Bit-exact replication of the fp32 reference recurrence:
//   err = fl(x_t - r);  pos = err > 0.1f;  neg = err < -0.1f;
//   spike = pos - neg;  r = fl(r + spike*0.1f)
// Chain per step: FADD(4) -> FSET(4) -> FFMA(4) -> FFMA(4) = 16 cycles.

constexpr int T_LEN = 131072;
constexpr int NSEQ  = 512;           // 64 * 8
constexpr int NB    = T_LEN / 4;     // float4 blocks per sequence
constexpr int DEPTH = 8;             // prefetch ring depth (8 * ~64cyc covers DRAM latency)

__device__ __forceinline__ float dm_step(float v, float& r, float thr, float nthr) {
    // err must be a plain FADD (single rounding), exactly as the reference.
    float err = v - r;
    float a, b;
    // FSET: float 0.0/1.0 output directly from the compare (one 4-cyc op,
    // instead of FSETP + FSEL which would add a level to the chain).
    asm("set.gt.f32.f32 %0, %1, %2;" : "=f"(a) : "f"(err), "f"(thr));
    asm("set.lt.f32.f32 %0, %1, %2;" : "=f"(b) : "f"(err), "f"(nthr));
    // a,b in {0,1}, mutually exclusive. Reproduces fl(r + spike*thr) exactly:
    //   a=1,b=0: fl(r + thr); a=0,b=1: fl(r,+0)=r then fl(r - thr); a=b=0: r.
    r = __fmaf_rn(a, thr,  r);
    r = __fmaf_rn(b, nthr, r);
    return a - b;   // spike in {-1, 0, +1}, exact
}

__global__ __launch_bounds__(32, 1)
void DeltaModulationEncoder_kernel(const float* __restrict__ x,
                                   float* __restrict__ out) {
    const int seq = blockIdx.x * 32 + threadIdx.x;   // one sequence per lane

    const float4* __restrict__ xin  =
        reinterpret_cast<const float4*>(x)   + (size_t)seq * NB;
    float4* __restrict__ oput =
        reinterpret_cast<float4*>(out)       + (size_t)seq * NB;

    const float thr  = 0.1f;
    const float nthr = -0.1f;

    // Register ring buffer: prefetch DEPTH float4 blocks ahead so global-load
    // latency stays off the 16-cyc/step dependency chain.
    float4 buf[DEPTH];
#pragma unroll
    for (int i = 0; i < DEPTH; i++) buf[i] = xin[i];

    float r = 0.0f;

    for (int b0 = 0; b0 < NB; b0 += DEPTH) {
#pragma unroll
        for (int j = 0; j < DEPTH; j++) {
            const float4 v = buf[j];
            const int pf = b0 + j + DEPTH;
            if (pf < NB) buf[j] = xin[pf];   // issue prefetch early, off-chain

            float4 s;
            s.x = dm_step(v.x, r, thr, nthr);
            s.y = dm_step(v.y, r, thr, nthr);
            s.z = dm_step(v.z, r, thr, nthr);
            s.w = dm_step(v.w, r, thr, nthr);

            oput[b0 + j] = s;
        }
    }
}

extern "C" void kernel_launch(void* const* d_in, const int* in_sizes, int n_in,
                              void* d_out, int out_size) {
    (void)in_sizes; (void)n_in; (void)out_size;
    const float* x = (const float*)d_in[0];
    float* out     = (float*)d_out;

    // 16 blocks of one warp each -> one warp per SM, fully chain-bound.
    DeltaModulationEncoder_kernel<<<NSEQ / 32, 32>>>(x, out);
}

// round 2
// speedup vs baseline: 1.1315x; 1.1315x over previous
#include <cuda_runtime.h>

// Delta modulation encoder: 512 independent serial scans of length 131072.
// Bit-exact fp32 replication of:
//   err = fl(x_t - r); p = err>0.1f; n = err<-0.1f; spike = p-n; r = fl(r + spike*0.1f)
//
// Carried state is the RESOLVED err. All three candidate next-errs
// (x_{t+1} - fl(r+0.1f), x_{t+1} - fl(r-0.1f), x_{t+1} - r) are precomputed
// one step ahead; each step is FSETP -> selp -> selp (all 4-cyc pred-as-data
// ops) = 16 cyc/step steady-state chain. The r-resolution / candidate / err
// FADD path (12 extra cycles) completes exactly when the next step's inner
// selp issues, so it never adds to the chain.

constexpr int T_LEN = 131072;
constexpr int NSEQ  = 512;          // 64 * 8
constexpr int NB    = T_LEN / 4;    // float4 blocks per sequence
constexpr int DEPTH = 16;           // ring depth: 16*4*16cyc ~= 1024 cyc >> DRAM 577

struct DMState {
    float err;              // resolved err_t (carried chain state)
    float rr;               // resolved recon (the "no-spike" candidate)
    float Cu, Cd;           // fl(rr + 0.1f), fl(rr - 0.1f)
    float Eu, Ed, Ez;       // x_{t+1} - {Cu, Cd, rr}
};

// One element. xnn = x_{t+2}. Returns spike_t as float in {-1,0,1}.
__device__ __forceinline__ float dm_step(DMState& s, float xnn) {
    float spike;
    asm("{\n\t"
        ".reg .pred p, n;\n\t"
        ".reg .f32  t0, t1, t2;\n\t"
        "setp.gt.f32 p, %1, 0f3DCCCCCD;\n\t"            // err >  0.1f
        "setp.lt.f32 n, %1, 0fBDCCCCCD;\n\t"            // err < -0.1f
        "selp.f32 t0, 0fBF800000, 0f00000000, n;\n\t"   // n ? -1 : 0
        "selp.f32 %0, 0f3F800000, t0, p;\n\t"           // spike = p ? 1 : t0
        "selp.f32 t1, %6, %7, n;\n\t"                   // n ? Ed : Ez
        "selp.f32 %1, %5, t1, p;\n\t"                   // err' = p ? Eu : t1   [chain]
        "selp.f32 t2, %4, %2, n;\n\t"                   // n ? Cd : rr
        "selp.f32 %2, %3, t2, p;\n\t"                   // rr'  = p ? Cu : t2
        "add.f32  %3, %2, 0f3DCCCCCD;\n\t"              // Cu' = fl(rr' + 0.1f)
        "add.f32  %4, %2, 0fBDCCCCCD;\n\t"              // Cd' = fl(rr' - 0.1f)
        "sub.f32  %5, %8, %3;\n\t"                      // Eu' = fl(xnn - Cu')
        "sub.f32  %6, %8, %4;\n\t"                      // Ed' = fl(xnn - Cd')
        "sub.f32  %7, %8, %2;\n\t"                      // Ez' = fl(xnn - rr')
        "}"
        : "=f"(spike),
          "+f"(s.err), "+f"(s.rr), "+f"(s.Cu), "+f"(s.Cd),
          "+f"(s.Eu), "+f"(s.Ed), "+f"(s.Ez)
        : "f"(xnn));
    return spike;
}

__global__ __launch_bounds__(32, 1)
void DeltaModulationEncoder_kernel(const float* __restrict__ x,
                                   float* __restrict__ out) {
    const int seq = blockIdx.x * 32 + threadIdx.x;   // one sequence per lane

    const float4* __restrict__ xin =
        reinterpret_cast<const float4*>(x)   + (size_t)seq * NB;
    float4* __restrict__ oput =
        reinterpret_cast<float4*>(out)       + (size_t)seq * NB;

    // Prefetch ring
    float4 buf[DEPTH];
#pragma unroll
    for (int i = 0; i < DEPTH; i++) buf[i] = xin[i];

    // Initial state (recon r0 = 0):
    //   err_0 = fl(x0 - 0) = x0
    //   candidates of r1: fl(0+0.1)=0.1f, fl(0-0.1)=-0.1f, 0
    //   candidate errs vs x1
    DMState st;
    {
        const float x0 = buf[0].x;
        const float x1 = buf[0].y;
        st.err = x0;
        st.rr  = 0.0f;
        st.Cu  = 0.1f;
        st.Cd  = -0.1f;
        st.Eu  = x1 - st.Cu;   // fl(x1 - 0.1f)
        st.Ed  = x1 - st.Cd;   // fl(x1 + 0.1f)
        st.Ez  = x1;           // fl(x1 - 0)
    }

    for (int j0 = 0; j0 < NB; j0 += DEPTH) {
#pragma unroll
        for (int jj = 0; jj < DEPTH; jj++) {
            const int j = j0 + jj;
            const float4 v = buf[jj];
            // Peek first two elements of block j+1 (slot untouched except
            // jj==DEPTH-1, where slot 0 was already refilled with block j+1).
            const float4 nb = buf[(jj + 1) & (DEPTH - 1)];

            const int pf = j + DEPTH;
            if (pf < NB) buf[jj] = xin[pf];   // refill, off-chain

            // element t=4j+k consumes xnn = x[t+2]
            float4 s;
            s.x = dm_step(st, v.z);
            s.y = dm_step(st, v.w);
            s.z = dm_step(st, nb.x);
            s.w = dm_step(st, nb.y);

            oput[j] = s;
        }
    }
}

extern "C" void kernel_launch(void* const* d_in, const int* in_sizes, int n_in,
                              void* d_out, int out_size) {
    (void)in_sizes; (void)n_in; (void)out_size;
    const float* x = (const float*)d_in[0];
    float* out     = (float*)d_out;

    // 16 blocks of one warp each: one warp per SM -> full 1 IPC issue budget
    // and full L1/LSU per warp.
    DeltaModulationEncoder_kernel<<<NSEQ / 32, 32>>>(x, out);
}

// round 3
// speedup vs baseline: 1.6460x; 1.4547x over previous
#include <cuda_runtime.h>
#include <cstdint>

// Delta modulation encoder: 512 independent serial scans of length 131072.
// Bit-exact fp32 replication of:
//   err = fl(x_t - r); p = err>0.1; n = err<-0.1; spike = p-n; r = fl(r + spike*0.1)
//
// R2 lesson: per-lane-contiguous LDG/STG = 32 wavefronts/instr = L1tex-bound.
// R3: stage all I/O through shared memory with coalesced cp.async / STG.
// The carried chain is FSETP -> selp -> selp = 12 cyc/step; everything else
// (candidate recon/err computation, spike materialization, smem traffic) is
// off-chain and bounded by the single warp's issue rate (~18 instr/step).

constexpr int T_LEN = 131072;
constexpr int NSEQ  = 512;            // 64 * 8
constexpr int TILE  = 64;             // time steps per lane per tile
constexpr int NT    = T_LEN / TILE;   // 2048 tiles
constexpr int ROWF  = TILE + 4;       // 68 floats = 272 B row stride (16B-aligned,
                                      // conflict-free LDS.128 across lanes)
constexpr int NBUF  = 4;              // input ring buffers (3 live + 1 idle)

struct DMState {
    float err;              // resolved err_t (chain state)
    float rr;               // resolved recon (no-spike candidate)
    float Cu, Cd;           // fl(rr+0.1f), fl(rr-0.1f)
    float Eu, Ed, Ez;       // x_{t+1} - {Cu, Cd, rr}
};

// One element. xnn = x[t+2]. Returns spike_t in {-1,0,1}. Bit-exact.
__device__ __forceinline__ float dm_step(DMState& s, float xnn) {
    float spike;
    asm("{\n\t"
        ".reg .pred p, n;\n\t"
        ".reg .f32  t0, t1, t2;\n\t"
        "setp.gt.f32 p, %1, 0f3DCCCCCD;\n\t"            // err >  0.1f
        "setp.lt.f32 n, %1, 0fBDCCCCCD;\n\t"            // err < -0.1f
        "selp.f32 t0, 0fBF800000, 0f00000000, n;\n\t"   // n ? -1 : 0
        "selp.f32 %0, 0f3F800000, t0, p;\n\t"           // spike
        "selp.f32 t1, %6, %7, n;\n\t"                   // n ? Ed : Ez
        "selp.f32 %1, %5, t1, p;\n\t"                   // err' (chain)
        "selp.f32 t2, %4, %2, n;\n\t"                   // n ? Cd : rr
        "selp.f32 %2, %3, t2, p;\n\t"                   // rr'
        "add.f32  %3, %2, 0f3DCCCCCD;\n\t"              // Cu' = fl(rr'+0.1f)
        "add.f32  %4, %2, 0fBDCCCCCD;\n\t"              // Cd' = fl(rr'-0.1f)
        "sub.f32  %5, %8, %3;\n\t"                      // Eu'
        "sub.f32  %6, %8, %4;\n\t"                      // Ed'
        "sub.f32  %7, %8, %2;\n\t"                      // Ez'
        "}"
        : "=f"(spike),
          "+f"(s.err), "+f"(s.rr), "+f"(s.Cu), "+f"(s.Cd),
          "+f"(s.Eu), "+f"(s.Ed), "+f"(s.Ez)
        : "f"(xnn));
    return spike;
}

__device__ __forceinline__ void cp_async16(uint32_t dst_smem, const void* src) {
    asm volatile("cp.async.cg.shared.global [%0], [%1], 16;"
                 :: "r"(dst_smem), "l"(src));
}
__device__ __forceinline__ void cp_commit() {
    asm volatile("cp.async.commit_group;" ::: "memory");
}
__device__ __forceinline__ void cp_wait1() {
    asm volatile("cp.async.wait_group 1;" ::: "memory");
}

__global__ __launch_bounds__(32, 1)
void DeltaModulationEncoder_kernel(const float* __restrict__ x,
                                   float* __restrict__ out) {
    __shared__ __align__(16) float sin_buf[NBUF][32 * ROWF];
    __shared__ __align__(16) float sout[32 * ROWF];

    const int lane    = threadIdx.x;
    const int seqbase = blockIdx.x * 32;

    // Cooperative-load mapping: instr i covers rows 2i, 2i+1 (256B each).
    const int half = lane >> 4;          // 0/1: which row within the pair
    const int colb = (lane & 15) * 16;   // 16B chunk within the 256B row

    // Global base for this thread's cooperative-load role (row offset added per i).
    const char* gsrc_base = (const char*)x
        + ((size_t)(seqbase + half) * T_LEN) * 4 + colb;
    char* gdst_base = (char*)out
        + ((size_t)(seqbase + half) * T_LEN) * 4 + colb;
    const size_t row2_stride = (size_t)2 * T_LEN * 4;   // advance 2 rows

    uint32_t sin_u32[NBUF];
#pragma unroll
    for (int b = 0; b < NBUF; b++)
        sin_u32[b] = (uint32_t)__cvta_generic_to_shared(&sin_buf[b][0]);

    // ---- issue one tile's coalesced loads into ring slot (tile & 3) ----
    auto issue_tile = [&](int tile) {
        if (tile < NT) {
            const uint32_t sbase = sin_u32[tile & (NBUF - 1)]
                                 + (uint32_t)(half * ROWF * 4 + colb);
            const char* g = gsrc_base + (size_t)tile * TILE * 4;
#pragma unroll
            for (int i = 0; i < 16; i++) {
                cp_async16(sbase + (uint32_t)(2 * i * ROWF * 4),
                           g + (size_t)i * row2_stride);
            }
        }
        cp_commit();
    };

    // Prologue: tiles 0 and 1 in flight; wait for tile 0.
    issue_tile(0);
    issue_tile(1);
    cp_wait1();           // <=1 pending -> tile 0 complete
    __syncwarp();

    // Initial state (recon r0 = 0) from x0, x1.
    DMState st;
    {
        const float x0 = sin_buf[0][lane * ROWF + 0];
        const float x1 = sin_buf[0][lane * ROWF + 1];
        st.err = x0;
        st.rr  = 0.0f;
        st.Cu  = 0.1f;
        st.Cd  = -0.1f;
        st.Eu  = x1 - st.Cu;
        st.Ed  = x1 - st.Cd;
        st.Ez  = x1;
    }

    for (int tile = 0; tile < NT; ++tile) {
        issue_tile(tile + 2);
        cp_wait1();       // <=1 pending -> tile+1 resident (needed for peek)
        __syncwarp();

        const float4* bk  = (const float4*)&sin_buf[tile & (NBUF - 1)][lane * ROWF];
        const float4* bk1 = (const float4*)&sin_buf[(tile + 1) & (NBUF - 1)][lane * ROWF];
        float4* so = (float4*)&sout[lane * ROWF];

        float4 cur = bk[0];
        float4 nxt = bk[1];

#pragma unroll
        for (int g = 0; g < 16; ++g) {
            // Prefetch group g+2 (crosses into tile+1 for g >= 14; beyond the
            // last tile this reads stale smem, which only feeds candidates for
            // steps past T-1 and never reaches the output).
            const float4 nn = (g < 14) ? bk[g + 2] : bk1[g - 14];

            float4 sp;
            sp.x = dm_step(st, cur.z);
            sp.y = dm_step(st, cur.w);
            sp.z = dm_step(st, nxt.x);
            sp.w = dm_step(st, nxt.y);
            so[g] = sp;               // STS.128, conflict-free

            cur = nxt;
            nxt = nn;
        }

        __syncwarp();                 // STS visible to all lanes

        // Coalesced flush: 32 rows x 256B.
        {
            const char* sob = (const char*)sout + half * ROWF * 4 + colb;
            char* g = gdst_base + (size_t)tile * TILE * 4;
#pragma unroll
            for (int i = 0; i < 16; i++) {
                float4 v = *(const float4*)(sob + (size_t)(2 * i) * ROWF * 4);
                *(float4*)(g + (size_t)i * row2_stride) = v;
            }
        }
        __syncwarp();                 // protect sout before next tile's STS
    }
}

extern "C" void kernel_launch(void* const* d_in, const int* in_sizes, int n_in,
                              void* d_out, int out_size) {
    (void)in_sizes; (void)n_in; (void)out_size;
    const float* x = (const float*)d_in[0];
    float* out     = (float*)d_out;

    DeltaModulationEncoder_kernel<<<NSEQ / 32, 32>>>(x, out);
}

// round 4
// speedup vs baseline: 1.9031x; 1.1562x over previous
#include <cuda_runtime.h>
#include <cstdint>

// Delta modulation encoder: 512 independent serial scans of length 131072.
// Bit-exact fp32 replication of:
//   err = fl(x_t - r); p = err>0.1; n = err<-0.1; spike = p-n; r = fl(r + spike*0.1)
//
// R3 lesson: single warp issues IN ORDER; the 16 STG.128 (12 cyc issue each)
// + 16 LDGSTS (8 cyc) + flush LDS per tile sat inside the compute stream and
// blocked the selp-chain (~6.5 cyc/step + boundary-burst stalls).
// R4: warp specialization. Warp 0 = pure compute (chain + LDS/STS only).
// Warp 1 = all cp.async input staging + all coalesced output flushing.
// Handshake via two named barriers per 64-step tile; sout double-buffered.

constexpr int T_LEN = 131072;
constexpr int NSEQ  = 512;            // 64 * 8
constexpr int TILE  = 64;             // time steps per lane per tile
constexpr int NT    = T_LEN / TILE;   // 2048 tiles
constexpr int ROWF  = TILE + 4;       // 68 floats = 272B row stride -> conflict-free LDS.128
constexpr int NBUF  = 3;              // input ring: t resident, t+1 resident, t+2 in flight

struct DMState {
    float err;              // resolved err_t (chain state)
    float rr;               // resolved recon (no-spike candidate)
    float Cu, Cd;           // fl(rr+0.1f), fl(rr-0.1f)
    float Eu, Ed, Ez;       // x_{t+1} - {Cu, Cd, rr}
};

// One element. xnn = x[t+2]. Returns spike_t in {-1,0,1}. Bit-exact.
__device__ __forceinline__ float dm_step(DMState& s, float xnn) {
    float spike;
    asm("{\n\t"
        ".reg .pred p, n;\n\t"
        ".reg .f32  t0, t1, t2;\n\t"
        "setp.gt.f32 p, %1, 0f3DCCCCCD;\n\t"            // err >  0.1f
        "setp.lt.f32 n, %1, 0fBDCCCCCD;\n\t"            // err < -0.1f
        "selp.f32 t0, 0fBF800000, 0f00000000, n;\n\t"   // n ? -1 : 0
        "selp.f32 %0, 0f3F800000, t0, p;\n\t"           // spike
        "selp.f32 t1, %6, %7, n;\n\t"                   // n ? Ed : Ez
        "selp.f32 %1, %5, t1, p;\n\t"                   // err' (chain)
        "selp.f32 t2, %4, %2, n;\n\t"                   // n ? Cd : rr
        "selp.f32 %2, %3, t2, p;\n\t"                   // rr'
        "add.f32  %3, %2, 0f3DCCCCCD;\n\t"              // Cu' = fl(rr'+0.1f)
        "add.f32  %4, %2, 0fBDCCCCCD;\n\t"              // Cd' = fl(rr'-0.1f)
        "sub.f32  %5, %8, %3;\n\t"                      // Eu'
        "sub.f32  %6, %8, %4;\n\t"                      // Ed'
        "sub.f32  %7, %8, %2;\n\t"                      // Ez'
        "}"
        : "=f"(spike),
          "+f"(s.err), "+f"(s.rr), "+f"(s.Cu), "+f"(s.Cd),
          "+f"(s.Eu), "+f"(s.Ed), "+f"(s.Ez)
        : "f"(xnn));
    return spike;
}

__device__ __forceinline__ void cp_async16(uint32_t dst_smem, const void* src) {
    asm volatile("cp.async.cg.shared.global [%0], [%1], 16;"
                 :: "r"(dst_smem), "l"(src));
}
__device__ __forceinline__ void cp_commit() {
    asm volatile("cp.async.commit_group;" ::: "memory");
}
__device__ __forceinline__ void cp_wait1() {
    asm volatile("cp.async.wait_group 1;" ::: "memory");
}
__device__ __forceinline__ void bar1() {
    asm volatile("bar.sync 1, 64;" ::: "memory");
}
__device__ __forceinline__ void bar2() {
    asm volatile("bar.sync 2, 64;" ::: "memory");
}

__global__ __launch_bounds__(64, 1)
void DeltaModulationEncoder_kernel(const float* __restrict__ x,
                                   float* __restrict__ out) {
    __shared__ __align__(16) float sin_buf[NBUF][32 * ROWF];   // 26.1 KB
    __shared__ __align__(16) float sout[2][32 * ROWF];         // 17.4 KB

    const int tid  = threadIdx.x;
    const int warp = tid >> 5;
    const int lane = tid & 31;
    const int seqbase = blockIdx.x * 32;

    if (warp == 1) {
        // ───────────────────────── I/O warp ─────────────────────────
        // Cooperative coalesced mapping: instr i covers rows 2i, 2i+1 (256B each).
        const int half = lane >> 4;
        const int colb = (lane & 15) * 16;
        const char* gsrc = (const char*)x
            + ((size_t)(seqbase + half) * T_LEN) * 4 + colb;
        char* gdst = (char*)out
            + ((size_t)(seqbase + half) * T_LEN) * 4 + colb;
        const size_t row2 = (size_t)2 * T_LEN * 4;

        uint32_t sin_addr[NBUF];
#pragma unroll
        for (int b = 0; b < NBUF; b++)
            sin_addr[b] = (uint32_t)__cvta_generic_to_shared(&sin_buf[b][0])
                        + (uint32_t)(half * ROWF * 4 + colb);

        // Prologue: tiles 0, 1 in flight (slots 0, 1).
#pragma unroll
        for (int t0 = 0; t0 < 2; t0++) {
            const char* g = gsrc + (size_t)t0 * TILE * 4;
            const uint32_t s = sin_addr[t0];
#pragma unroll
            for (int i = 0; i < 16; i++)
                cp_async16(s + (uint32_t)(2 * i * ROWF * 4), g + (size_t)i * row2);
            cp_commit();
        }

        int slot_w = 2;   // ring slot for tile t+2
        for (int t = 0; t < NT; ++t) {
            if (t + 2 < NT) {
                const char* g = gsrc + (size_t)(t + 2) * TILE * 4;
                const uint32_t s = sin_addr[slot_w];
#pragma unroll
                for (int i = 0; i < 16; i++)
                    cp_async16(s + (uint32_t)(2 * i * ROWF * 4), g + (size_t)i * row2);
            }
            cp_commit();
            cp_wait1();                 // tiles t, t+1 resident
            bar1();                     // release compute for tile t

            if (t > 0) {                // flush sout[(t-1)&1]
                const float* sob = &sout[(t - 1) & 1][0] + half * ROWF + (colb >> 2);
                char* g = gdst + (size_t)(t - 1) * TILE * 4;
#pragma unroll
                for (int i = 0; i < 16; i++) {
                    float4 v = *(const float4*)(sob + 2 * i * ROWF);
                    *(float4*)(g + (size_t)i * row2) = v;
                }
            }
            bar2();                     // buffer (t-1)&1 reusable; tile t STS visible
            slot_w = (slot_w + 1 == NBUF) ? 0 : slot_w + 1;
        }
        // Final flush: tile NT-1.
        {
            const float* sob = &sout[(NT - 1) & 1][0] + half * ROWF + (colb >> 2);
            char* g = gdst + (size_t)(NT - 1) * TILE * 4;
#pragma unroll
            for (int i = 0; i < 16; i++) {
                float4 v = *(const float4*)(sob + 2 * i * ROWF);
                *(float4*)(g + (size_t)i * row2) = v;
            }
        }
    } else {
        // ──────────────────────── compute warp ────────────────────────
        DMState st;
        int s0 = 0;
        for (int t = 0; t < NT; ++t) {
            const int s1 = (s0 + 1 == NBUF) ? 0 : s0 + 1;
            bar1();                     // tiles t (slot s0), t+1 (slot s1) resident

            if (t == 0) {               // recon r0 = 0
                const float x0 = sin_buf[0][lane * ROWF + 0];
                const float x1 = sin_buf[0][lane * ROWF + 1];
                st.err = x0;
                st.rr  = 0.0f;
                st.Cu  = 0.1f;
                st.Cd  = -0.1f;
                st.Eu  = x1 - st.Cu;
                st.Ed  = x1 - st.Cd;
                st.Ez  = x1;
            }

            const float4* bk  = (const float4*)&sin_buf[s0][lane * ROWF];
            const float4* bk1 = (const float4*)&sin_buf[s1][lane * ROWF];
            float4* so = (float4*)&sout[t & 1][lane * ROWF];

            float4 cur = bk[0];
            float4 nxt = bk[1];
#pragma unroll
            for (int g = 0; g < 16; ++g) {
                // group g+2 (peeks into tile t+1 for g>=14; beyond the last
                // tile this is stale smem feeding only never-output candidates)
                const float4 nn = (g < 14) ? bk[g + 2] : bk1[g - 14];

                float4 sp;
                sp.x = dm_step(st, cur.z);
                sp.y = dm_step(st, cur.w);
                sp.z = dm_step(st, nxt.x);
                sp.w = dm_step(st, nxt.y);
                so[g] = sp;             // STS.128, conflict-free

                cur = nxt;
                nxt = nn;
            }
            bar2();                     // hand buffer t&1 to the I/O warp
            s0 = s1;
        }
    }
}

extern "C" void kernel_launch(void* const* d_in, const int* in_sizes, int n_in,
                              void* d_out, int out_size) {
    (void)in_sizes; (void)n_in; (void)out_size;
    const float* x = (const float*)d_in[0];
    float* out     = (float*)d_out;

    // 16 blocks x 64 threads: one compute warp + one I/O warp per SM.
    DeltaModulationEncoder_kernel<<<NSEQ / 32, 64>>>(x, out);
}

// round 6
// speedup vs baseline: 1.9286x; 1.0134x over previous
#include <cuda_runtime.h>
#include <cstdint>

// Delta modulation encoder: 512 independent serial scans of length 131072.
// Bit-exact fp32 replication of:
//   err = fl(x_t - r); p = err>0.1; n = err<-0.1; spike = p-n; r = fl(r + spike*0.1)
//
// R4 lesson: we are per-SMSP PIPE-throughput-bound (rt=2 cyc/op); 13 ops/step
// mostly on one pipe -> 26+ cyc/step. R5: 12 ops/step, balanced 6 alu-class
// (setp/selp) + 6 fma-class (ffma/fadd/fsub). rr update is a single exact
// FFMA(spike, theta, rr): spike*theta is exact, so one rounding = reference.
// Cu/Cd are now step-local; carried state is {err, rr, Eu, Ed, Ez}.
// (R5 bench was an infra failure; this is the same kernel resubmitted.)

constexpr int T_LEN = 131072;
constexpr int NSEQ  = 512;            // 64 * 8
constexpr int TILE  = 64;             // time steps per lane per tile
constexpr int NT    = T_LEN / TILE;   // 2048 tiles
constexpr int ROWF  = TILE + 4;       // 272B row stride -> conflict-free LDS.128
constexpr int NBUF  = 3;              // input ring: t, t+1 resident, t+2 in flight

struct DMState {
    float err;              // resolved err_t (chain state)
    float rr;               // resolved recon
    float Eu, Ed, Ez;       // x_{t+1} - {fl(rr+0.1), fl(rr-0.1), rr}
};

// One element. xnn = x[t+2]. Returns spike_t in {-1,0,1}. Bit-exact.
__device__ __forceinline__ float dm_step(DMState& s, float xnn) {
    float spike;
    asm("{\n\t"
        ".reg .pred p, n;\n\t"
        ".reg .f32  t0, t1, cu, cd;\n\t"
        "setp.gt.f32 p, %1, 0f3DCCCCCD;\n\t"            // err >  0.1f
        "setp.lt.f32 n, %1, 0fBDCCCCCD;\n\t"            // err < -0.1f
        "selp.f32 t0, 0fBF800000, 0f00000000, n;\n\t"   // n ? -1 : 0
        "selp.f32 %0, 0f3F800000, t0, p;\n\t"           // spike
        "selp.f32 t1, %4, %5, n;\n\t"                   // n ? Ed : Ez
        "selp.f32 %1, %3, t1, p;\n\t"                   // err' (chain)
        "fma.rn.f32 %2, %0, 0f3DCCCCCD, %2;\n\t"        // rr' = fl(rr + spike*0.1f)
        "add.f32  cu, %2, 0f3DCCCCCD;\n\t"              // fl(rr'+0.1f)
        "add.f32  cd, %2, 0fBDCCCCCD;\n\t"              // fl(rr'-0.1f)
        "sub.f32  %3, %6, cu;\n\t"                      // Eu'
        "sub.f32  %4, %6, cd;\n\t"                      // Ed'
        "sub.f32  %5, %6, %2;\n\t"                      // Ez'
        "}"
        : "=f"(spike),
          "+f"(s.err), "+f"(s.rr),
          "+f"(s.Eu), "+f"(s.Ed), "+f"(s.Ez)
        : "f"(xnn));
    return spike;
}

__device__ __forceinline__ void cp_async16(uint32_t dst_smem, const void* src) {
    asm volatile("cp.async.cg.shared.global [%0], [%1], 16;"
                 :: "r"(dst_smem), "l"(src));
}
__device__ __forceinline__ void cp_commit() {
    asm volatile("cp.async.commit_group;" ::: "memory");
}
__device__ __forceinline__ void cp_wait1() {
    asm volatile("cp.async.wait_group 1;" ::: "memory");
}
__device__ __forceinline__ void bar1() {
    asm volatile("bar.sync 1, 64;" ::: "memory");
}
__device__ __forceinline__ void bar2() {
    asm volatile("bar.sync 2, 64;" ::: "memory");
}

__global__ __launch_bounds__(64, 1)
void DeltaModulationEncoder_kernel(const float* __restrict__ x,
                                   float* __restrict__ out) {
    __shared__ __align__(16) float sin_buf[NBUF][32 * ROWF];
    __shared__ __align__(16) float sout[2][32 * ROWF];

    const int tid  = threadIdx.x;
    const int warp = tid >> 5;
    const int lane = tid & 31;
    const int seqbase = blockIdx.x * 32;

    if (warp == 1) {
        // ───────────────────────── I/O warp ─────────────────────────
        const int half = lane >> 4;
        const int colb = (lane & 15) * 16;
        const char* gsrc = (const char*)x
            + ((size_t)(seqbase + half) * T_LEN) * 4 + colb;
        char* gdst = (char*)out
            + ((size_t)(seqbase + half) * T_LEN) * 4 + colb;
        const size_t row2 = (size_t)2 * T_LEN * 4;

        uint32_t sin_addr[NBUF];
#pragma unroll
        for (int b = 0; b < NBUF; b++)
            sin_addr[b] = (uint32_t)__cvta_generic_to_shared(&sin_buf[b][0])
                        + (uint32_t)(half * ROWF * 4 + colb);

#pragma unroll
        for (int t0 = 0; t0 < 2; t0++) {
            const char* g = gsrc + (size_t)t0 * TILE * 4;
            const uint32_t s = sin_addr[t0];
#pragma unroll
            for (int i = 0; i < 16; i++)
                cp_async16(s + (uint32_t)(2 * i * ROWF * 4), g + (size_t)i * row2);
            cp_commit();
        }

        int slot_w = 2;
        for (int t = 0; t < NT; ++t) {
            if (t + 2 < NT) {
                const char* g = gsrc + (size_t)(t + 2) * TILE * 4;
                const uint32_t s = sin_addr[slot_w];
#pragma unroll
                for (int i = 0; i < 16; i++)
                    cp_async16(s + (uint32_t)(2 * i * ROWF * 4), g + (size_t)i * row2);
            }
            cp_commit();
            cp_wait1();                 // tiles t, t+1 resident
            bar1();                     // release compute for tile t

            if (t > 0) {                // flush sout[(t-1)&1]
                const float* sob = &sout[(t - 1) & 1][0] + half * ROWF + (colb >> 2);
                char* g = gdst + (size_t)(t - 1) * TILE * 4;
#pragma unroll
                for (int i = 0; i < 16; i++) {
                    float4 v = *(const float4*)(sob + 2 * i * ROWF);
                    *(float4*)(g + (size_t)i * row2) = v;
                }
            }
            bar2();                     // buffer reusable; tile t STS visible
            slot_w = (slot_w + 1 == NBUF) ? 0 : slot_w + 1;
        }
        {
            const float* sob = &sout[(NT - 1) & 1][0] + half * ROWF + (colb >> 2);
            char* g = gdst + (size_t)(NT - 1) * TILE * 4;
#pragma unroll
            for (int i = 0; i < 16; i++) {
                float4 v = *(const float4*)(sob + 2 * i * ROWF);
                *(float4*)(g + (size_t)i * row2) = v;
            }
        }
    } else {
        // ──────────────────────── compute warp ────────────────────────
        DMState st;
        int s0 = 0;
        for (int t = 0; t < NT; ++t) {
            const int s1 = (s0 + 1 == NBUF) ? 0 : s0 + 1;
            bar1();                     // tiles t (slot s0), t+1 (slot s1) resident

            if (t == 0) {               // recon r0 = 0
                const float x0 = sin_buf[0][lane * ROWF + 0];
                const float x1 = sin_buf[0][lane * ROWF + 1];
                st.err = x0;
                st.rr  = 0.0f;
                st.Eu  = x1 - 0.1f;     // fl(x1 - fl(0+0.1))
                st.Ed  = x1 + 0.1f;     // fl(x1 - fl(0-0.1))
                st.Ez  = x1;            // fl(x1 - 0)
            }

            const float4* bk  = (const float4*)&sin_buf[s0][lane * ROWF];
            const float4* bk1 = (const float4*)&sin_buf[s1][lane * ROWF];
            float4* so = (float4*)&sout[t & 1][lane * ROWF];

            float4 cur = bk[0];
            float4 nxt = bk[1];
#pragma unroll
            for (int g = 0; g < 16; ++g) {
                // group g+2 (peeks into tile t+1 for g>=14; beyond the last
                // tile this is stale smem feeding only never-output candidates)
                const float4 nn = (g < 14) ? bk[g + 2] : bk1[g - 14];

                float4 sp;
                sp.x = dm_step(st, cur.z);
                sp.y = dm_step(st, cur.w);
                sp.z = dm_step(st, nxt.x);
                sp.w = dm_step(st, nxt.y);
                so[g] = sp;             // STS.128, conflict-free

                cur = nxt;
                nxt = nn;
            }
            bar2();                     // hand buffer t&1 to the I/O warp
            s0 = s1;
        }
    }
}

extern "C" void kernel_launch(void* const* d_in, const int* in_sizes, int n_in,
                              void* d_out, int out_size) {
    (void)in_sizes; (void)n_in; (void)out_size;
    const float* x = (const float*)d_in[0];
    float* out     = (float*)d_out;

    DeltaModulationEncoder_kernel<<<NSEQ / 32, 64>>>(x, out);
}